// round 4
// baseline (speedup 1.0000x reference)
#include <cuda_runtime.h>
#include <cuda_bf16.h>

// TimeFeatureEmbedding: y = x @ W^T + b  ([B,T,4] x [512,4] -> [B,T,512]),
// then broadcast each (b,t) row S times -> [B,T,S,512].
//
// Pure store-bandwidth kernel: 402.7 MB of output stores, ~60 KB of input
// reads, 16 FMAs per thread. One CTA per (b,t) row; each thread holds its
// float4 slice of the row in registers and streams S*128/256 STG.128 stores.

__global__ __launch_bounds__(256, 8)
void tfe_broadcast_kernel(const float* __restrict__ x,
                          const float* __restrict__ W,
                          const float* __restrict__ b,
                          float* __restrict__ out,
                          int S)
{
    const int bt  = blockIdx.x;      // which (b,t) row
    const int tid = threadIdx.x;
    const int d4  = tid & 127;       // float4 index within D_MODEL=512 (128 float4s)

    // x row: 4 floats, broadcast across the CTA (L1-cached)
    const float4 x4 = __ldg(reinterpret_cast<const float4*>(x) + bt);

    // bias slice
    const float4 b4 = __ldg(reinterpret_cast<const float4*>(b) + d4);

    // W rows d = 4*d4 .. 4*d4+3, each row is 4 contiguous floats = one float4
    const float4* W4 = reinterpret_cast<const float4*>(W);
    const float4 w0 = __ldg(W4 + d4 * 4 + 0);
    const float4 w1 = __ldg(W4 + d4 * 4 + 1);
    const float4 w2 = __ldg(W4 + d4 * 4 + 2);
    const float4 w3 = __ldg(W4 + d4 * 4 + 3);

    float4 y4;
    y4.x = fmaf(x4.x, w0.x, fmaf(x4.y, w0.y, fmaf(x4.z, w0.z, fmaf(x4.w, w0.w, b4.x))));
    y4.y = fmaf(x4.x, w1.x, fmaf(x4.y, w1.y, fmaf(x4.z, w1.z, fmaf(x4.w, w1.w, b4.y))));
    y4.z = fmaf(x4.x, w2.x, fmaf(x4.y, w2.y, fmaf(x4.z, w2.z, fmaf(x4.w, w2.w, b4.z))));
    y4.w = fmaf(x4.x, w3.x, fmaf(x4.y, w3.y, fmaf(x4.z, w3.z, fmaf(x4.w, w3.w, b4.w))));

    // Output region for this (b,t): S * 512 floats = S * 128 float4, contiguous.
    // Stride 256 is a multiple of 128, so (i & 127) == d4 for every iteration:
    // the same register value is stored each time. Warp writes 512B contiguous.
    float4* out4 = reinterpret_cast<float4*>(out) + (size_t)bt * (size_t)S * 128u;
    const int n4 = S * 128;

    #pragma unroll 4
    for (int i = tid; i < n4; i += 256) {
        __stcs(out4 + i, y4);   // streaming store: no L2 reuse, evict-first
    }
}

extern "C" void kernel_launch(void* const* d_in, const int* in_sizes, int n_in,
                              void* d_out, int out_size)
{
    // Input order per reference setup_inputs: x [B,T,4] f32, S (int scalar),
    // W [512,4] f32, b [512] f32. Output: [B,T,S,512] f32.
    const float* x = (const float*)d_in[0];
    const float* W = (const float*)d_in[2];
    const float* b = (const float*)d_in[3];
    float* out = (float*)d_out;

    const int BT = in_sizes[0] / 4;                 // B*T rows (d_inp = 4)
    const int S  = out_size / (BT * 512);           // recover S arithmetically

    tfe_broadcast_kernel<<<BT, 256>>>(x, W, b, out, S);
}

// round 5
// speedup vs baseline: 1.0104x; 1.0104x over previous
#include <cuda_runtime.h>
#include <cuda_bf16.h>

// TimeFeatureEmbedding: y = x @ W^T + b  ([B,T,4] x [512,4] -> [B,T,512]),
// then broadcast each (b,t) row S times -> [B,T,S,512].
//
// Pure store-bandwidth kernel: 402.7 MB of output stores, ~60 KB of input
// reads, 16 FMAs per thread. One CTA per (b,t) row; each thread holds its
// float4 slice of the row in registers and streams S*128/256 STG.128 stores.

__global__ __launch_bounds__(256, 8)
void tfe_broadcast_kernel(const float* __restrict__ x,
                          const float* __restrict__ W,
                          const float* __restrict__ b,
                          float* __restrict__ out,
                          int S)
{
    const int bt  = blockIdx.x;      // which (b,t) row
    const int tid = threadIdx.x;
    const int d4  = tid & 127;       // float4 index within D_MODEL=512 (128 float4s)

    // x row: 4 floats, broadcast across the CTA (L1-cached)
    const float4 x4 = __ldg(reinterpret_cast<const float4*>(x) + bt);

    // bias slice
    const float4 b4 = __ldg(reinterpret_cast<const float4*>(b) + d4);

    // W rows d = 4*d4 .. 4*d4+3, each row is 4 contiguous floats = one float4
    const float4* W4 = reinterpret_cast<const float4*>(W);
    const float4 w0 = __ldg(W4 + d4 * 4 + 0);
    const float4 w1 = __ldg(W4 + d4 * 4 + 1);
    const float4 w2 = __ldg(W4 + d4 * 4 + 2);
    const float4 w3 = __ldg(W4 + d4 * 4 + 3);

    float4 y4;
    y4.x = fmaf(x4.x, w0.x, fmaf(x4.y, w0.y, fmaf(x4.z, w0.z, fmaf(x4.w, w0.w, b4.x))));
    y4.y = fmaf(x4.x, w1.x, fmaf(x4.y, w1.y, fmaf(x4.z, w1.z, fmaf(x4.w, w1.w, b4.y))));
    y4.z = fmaf(x4.x, w2.x, fmaf(x4.y, w2.y, fmaf(x4.z, w2.z, fmaf(x4.w, w2.w, b4.z))));
    y4.w = fmaf(x4.x, w3.x, fmaf(x4.y, w3.y, fmaf(x4.z, w3.z, fmaf(x4.w, w3.w, b4.w))));

    // Output region for this (b,t): S * 512 floats = S * 128 float4, contiguous.
    // Stride 256 is a multiple of 128, so (i & 127) == d4 for every iteration:
    // the same register value is stored each time. Warp writes 512B contiguous.
    float4* out4 = reinterpret_cast<float4*>(out) + (size_t)bt * (size_t)S * 128u;
    const int n4 = S * 128;

    #pragma unroll 4
    for (int i = tid; i < n4; i += 256) {
        __stcs(out4 + i, y4);   // streaming store: no L2 reuse, evict-first
    }
}

extern "C" void kernel_launch(void* const* d_in, const int* in_sizes, int n_in,
                              void* d_out, int out_size)
{
    // Input order per reference setup_inputs: x [B,T,4] f32, S (int scalar),
    // W [512,4] f32, b [512] f32. Output: [B,T,S,512] f32.
    const float* x = (const float*)d_in[0];
    const float* W = (const float*)d_in[2];
    const float* b = (const float*)d_in[3];
    float* out = (float*)d_out;

    const int BT = in_sizes[0] / 4;                 // B*T rows (d_inp = 4)
    const int S  = out_size / (BT * 512);           // recover S arithmetically

    tfe_broadcast_kernel<<<BT, 256>>>(x, W, b, out, S);
}